// round 5
// baseline (speedup 1.0000x reference)
#include <cuda_runtime.h>
#include <math.h>

#define Bn 32
#define Qn 2000
#define Gn 64
#define Cn 80
#define LISTN 16

// Scratch
__device__ float g_costT[Bn * Gn * Qn];            // [b][g][q]
__device__ float g_iouT [Bn * Gn * Qn];            // [b][g][q]
__device__ int   g_gmin [Bn * Qn];                 // first argmin over g of cost row
__device__ int   g_list [Bn * Gn * LISTN];         // per-gt 16 smallest-cost query ids, sorted (v,idx)
__device__ int   g_selk [Bn * Gn];                 // dynamic k per gt
__device__ unsigned long long g_match[Bn * Qn];    // final match bitmask per query

// ---------------------------------------------------------------------------
// ordered-float <-> uint transforms (ascending order preserving)
// ---------------------------------------------------------------------------
__device__ __forceinline__ unsigned int ordf(float f) {
    unsigned int u = __float_as_uint(f);
    return (u & 0x80000000u) ? ~u : (u | 0x80000000u);
}
__device__ __forceinline__ float unordf(unsigned int o) {
    unsigned int u = (o & 0x80000000u) ? (o ^ 0x80000000u) : ~o;
    return __uint_as_float(u);
}

// ---------------------------------------------------------------------------
// Stage A: pairwise cost + iou + row argmin
// ---------------------------------------------------------------------------
__global__ void stageA(const float* __restrict__ logits,   // [B,Q,C]
                       const float* __restrict__ boxes,    // [B,Q,4]
                       const int*   __restrict__ gtcls,    // [B,G]
                       const float* __restrict__ gtbox,    // [B,G,4]
                       const float* __restrict__ szout,    // [B,4]
                       const float* __restrict__ sztgt)    // [B,G,4]
{
    int b = blockIdx.x;
    int q = blockIdx.y * blockDim.x + threadIdx.x;

    __shared__ float sg[Gn * 4];
    __shared__ float st[Gn * 4];
    __shared__ int   sc[Gn];
    for (int i = threadIdx.x; i < Gn * 4; i += blockDim.x) {
        sg[i] = gtbox[b * Gn * 4 + i];
        st[i] = sztgt[b * Gn * 4 + i];
    }
    for (int i = threadIdx.x; i < Gn; i += blockDim.x) sc[i] = gtcls[b * Gn + i];
    __syncthreads();
    if (q >= Qn) return;

    const float* bp = boxes + (size_t)(b * Qn + q) * 4;
    float x1 = bp[0], y1 = bp[1], x2 = bp[2], y2 = bp[3];
    float cx = (x1 + x2) * 0.5f, cy = (y1 + y2) * 0.5f;
    float areaA = (x2 - x1) * (y2 - y1);

    bool anyIB = false, anyIC = false;
    for (int g = 0; g < Gn; g++) {
        float gx1 = sg[g * 4], gy1 = sg[g * 4 + 1], gx2 = sg[g * 4 + 2], gy2 = sg[g * 4 + 3];
        bool ib = (cx > gx1) && (cx < gx2) && (cy > gy1) && (cy < gy2);
        float gcx = (gx1 + gx2) * 0.5f, gcy = (gy1 + gy2) * 0.5f;
        float gw = gx2 - gx1, gh = gy2 - gy1;
        bool ic = (cx > gcx - 2.5f * gw) && (cx < gcx + 2.5f * gw) &&
                  (cy > gcy - 2.5f * gh) && (cy < gcy + 2.5f * gh);
        anyIB |= ib; anyIC |= ic;
    }
    float fgpen = (anyIB || anyIC) ? 0.f : 1e4f;

    float so0 = szout[b * 4], so1 = szout[b * 4 + 1], so2 = szout[b * 4 + 2], so3 = szout[b * 4 + 3];
    float nx1 = x1 / so0, ny1 = y1 / so1, nx2 = x2 / so2, ny2 = y2 / so3;
    const float* lr = logits + (size_t)(b * Qn + q) * Cn;

    float* costOut = g_costT + (size_t)b * Gn * Qn;
    float* iouOut  = g_iouT  + (size_t)b * Gn * Qn;

    float best = 3.4e38f; int bidx = 0;
    for (int g = 0; g < Gn; g++) {
        float gx1 = sg[g * 4], gy1 = sg[g * 4 + 1], gx2 = sg[g * 4 + 2], gy2 = sg[g * 4 + 3];
        float areaB = (gx2 - gx1) * (gy2 - gy1);
        float ix1 = fmaxf(x1, gx1), iy1 = fmaxf(y1, gy1);
        float ix2 = fminf(x2, gx2), iy2 = fminf(y2, gy2);
        float iw = fmaxf(ix2 - ix1, 0.f), ih = fmaxf(iy2 - iy1, 0.f);
        float inter = iw * ih;
        float uni = areaA + areaB - inter;
        float iou = inter / uni;
        float ex1 = fminf(x1, gx1), ey1 = fminf(y1, gy1);
        float ex2 = fmaxf(x2, gx2), ey2 = fmaxf(y2, gy2);
        float ew = fmaxf(ex2 - ex1, 0.f), eh = fmaxf(ey2 - ey1, 0.f);
        float areaC = ew * eh;
        float giou = iou - (areaC - uni) / areaC;

        bool ib = (cx > gx1) && (cx < gx2) && (cy > gy1) && (cy < gy2);
        float gcx = (gx1 + gx2) * 0.5f, gcy = (gy1 + gy2) * 0.5f;
        float gw = gx2 - gx1, gh = gy2 - gy1;
        bool ic = (cx > gcx - 2.5f * gw) && (cx < gcx + 2.5f * gw) &&
                  (cy > gcy - 2.5f * gh) && (cy < gcy + 2.5f * gh);
        bool inbc = ib && ic;

        float p = lr[sc[g]];
        float pos = 0.25f * (1.f - p) * (1.f - p) * (-logf(p + 1e-8f));
        float neg = 0.75f * p * p * (-logf(1.f - p + 1e-8f));
        float ccost = pos - neg;

        float t0 = st[g * 4], t1 = st[g * 4 + 1], t2 = st[g * 4 + 2], t3 = st[g * 4 + 3];
        float cb = fabsf(nx1 - gx1 / t0) + fabsf(ny1 - gy1 / t1) +
                   fabsf(nx2 - gx2 / t2) + fabsf(ny2 - gy2 / t3);

        float cost = 5.f * cb + 2.f * ccost + 2.f * (-giou) + (inbc ? 0.f : 100.f) + fgpen;
        costOut[(size_t)g * Qn + q] = cost;
        iouOut [(size_t)g * Qn + q] = iou;
        if (cost < best) { best = cost; bidx = g; }   // first-occurrence min
    }
    g_gmin[b * Qn + q] = bidx;
}

// ---------------------------------------------------------------------------
// Stage Sel: one block per (b,g). Sorted register runs + 256-way merge.
// ---------------------------------------------------------------------------
#define SWP(x, y) { if ((y) < (x)) { unsigned long long _t = (x); (x) = (y); (y) = _t; } }

__device__ __forceinline__ unsigned long long blockMinU64(
    unsigned long long v, unsigned long long* s_w, unsigned long long* s_best,
    int lane, int wid, int nw)
{
    for (int off = 16; off; off >>= 1) {
        unsigned long long o = __shfl_down_sync(0xffffffffu, v, off);
        if (o < v) v = o;
    }
    if (lane == 0) s_w[wid] = v;
    __syncthreads();
    if (threadIdx.x == 0) {
        unsigned long long bb = s_w[0];
        for (int w = 1; w < nw; w++) if (s_w[w] < bb) bb = s_w[w];
        *s_best = bb;
    }
    __syncthreads();
    return *s_best;
}

__global__ __launch_bounds__(256) void stageSel()
{
    int bg = blockIdx.x;
    int tid = threadIdx.x, lane = tid & 31, wid = tid >> 5;

    __shared__ unsigned long long s_run[256 * 8];
    __shared__ unsigned long long s_w[8];
    __shared__ unsigned long long s_best;

    const float* ic = g_iouT  + (size_t)bg * Qn;
    const float* cc = g_costT + (size_t)bg * Qn;
    const unsigned long long SENT = ~0ull;

    // ---------- phase 1: top-5 iou (descending keys) ----------
    unsigned long long k0, k1, k2, k3, k4, k5, k6, k7;
    {
        int q;
        q = tid + 0 * 256; k0 = ((unsigned long long)(~ordf(ic[q])) << 32) | (unsigned)q;
        q = tid + 1 * 256; k1 = ((unsigned long long)(~ordf(ic[q])) << 32) | (unsigned)q;
        q = tid + 2 * 256; k2 = ((unsigned long long)(~ordf(ic[q])) << 32) | (unsigned)q;
        q = tid + 3 * 256; k3 = ((unsigned long long)(~ordf(ic[q])) << 32) | (unsigned)q;
        q = tid + 4 * 256; k4 = ((unsigned long long)(~ordf(ic[q])) << 32) | (unsigned)q;
        q = tid + 5 * 256; k5 = ((unsigned long long)(~ordf(ic[q])) << 32) | (unsigned)q;
        q = tid + 6 * 256; k6 = ((unsigned long long)(~ordf(ic[q])) << 32) | (unsigned)q;
        q = tid + 7 * 256; k7 = (q < Qn) ? (((unsigned long long)(~ordf(ic[q])) << 32) | (unsigned)q) : SENT;
    }
    // Batcher odd-even mergesort, 8 elements, 19 CEs
    SWP(k0,k1) SWP(k2,k3) SWP(k4,k5) SWP(k6,k7)
    SWP(k0,k2) SWP(k1,k3) SWP(k4,k6) SWP(k5,k7)
    SWP(k1,k2) SWP(k5,k6)
    SWP(k0,k4) SWP(k1,k5) SWP(k2,k6) SWP(k3,k7)
    SWP(k2,k4) SWP(k3,k5)
    SWP(k1,k2) SWP(k3,k4) SWP(k5,k6)
    s_run[tid*8+0]=k0; s_run[tid*8+1]=k1; s_run[tid*8+2]=k2; s_run[tid*8+3]=k3;
    s_run[tid*8+4]=k4; s_run[tid*8+5]=k5; s_run[tid*8+6]=k6; s_run[tid*8+7]=k7;
    __syncthreads();

    unsigned long long myhead = k0;
    int ptr = 0;
    float sum = 0.f;
    for (int pass = 0; pass < 5; pass++) {
        unsigned long long best = blockMinU64(myhead, s_w, &s_best, lane, wid, 8);
        sum += unordf(~(unsigned int)(best >> 32));          // descending order, == top_k sum
        if (myhead == best) {
            ptr++;
            myhead = (ptr < 8) ? s_run[tid * 8 + ptr] : SENT;
        }
    }
    int kdyn = (int)sum;          // truncating cast, as in the reference
    if (kdyn < 1) kdyn = 1;
    if (kdyn > 5) kdyn = 5;
    if (tid == 0) g_selk[bg] = kdyn;
    __syncthreads();              // s_run reuse barrier

    // ---------- phase 2: 16 smallest costs (ascending keys) ----------
    {
        int q;
        q = tid + 0 * 256; k0 = ((unsigned long long)ordf(cc[q]) << 32) | (unsigned)q;
        q = tid + 1 * 256; k1 = ((unsigned long long)ordf(cc[q]) << 32) | (unsigned)q;
        q = tid + 2 * 256; k2 = ((unsigned long long)ordf(cc[q]) << 32) | (unsigned)q;
        q = tid + 3 * 256; k3 = ((unsigned long long)ordf(cc[q]) << 32) | (unsigned)q;
        q = tid + 4 * 256; k4 = ((unsigned long long)ordf(cc[q]) << 32) | (unsigned)q;
        q = tid + 5 * 256; k5 = ((unsigned long long)ordf(cc[q]) << 32) | (unsigned)q;
        q = tid + 6 * 256; k6 = ((unsigned long long)ordf(cc[q]) << 32) | (unsigned)q;
        q = tid + 7 * 256; k7 = (q < Qn) ? (((unsigned long long)ordf(cc[q]) << 32) | (unsigned)q) : SENT;
    }
    SWP(k0,k1) SWP(k2,k3) SWP(k4,k5) SWP(k6,k7)
    SWP(k0,k2) SWP(k1,k3) SWP(k4,k6) SWP(k5,k7)
    SWP(k1,k2) SWP(k5,k6)
    SWP(k0,k4) SWP(k1,k5) SWP(k2,k6) SWP(k3,k7)
    SWP(k2,k4) SWP(k3,k5)
    SWP(k1,k2) SWP(k3,k4) SWP(k5,k6)
    s_run[tid*8+0]=k0; s_run[tid*8+1]=k1; s_run[tid*8+2]=k2; s_run[tid*8+3]=k3;
    s_run[tid*8+4]=k4; s_run[tid*8+5]=k5; s_run[tid*8+6]=k6; s_run[tid*8+7]=k7;
    __syncthreads();

    myhead = k0;
    ptr = 0;
    for (int pass = 0; pass < LISTN; pass++) {
        unsigned long long best = blockMinU64(myhead, s_w, &s_best, lane, wid, 8);
        if (tid == 0) g_list[bg * LISTN + pass] = (int)(unsigned int)(best & 0xffffffffu);
        if (myhead == best) {
            ptr++;
            myhead = (ptr < 8) ? s_run[tid * 8 + ptr] : SENT;
        }
    }
}

// ---------------------------------------------------------------------------
// Stage B2: one block per image; dedup + bounded refinement via sorted lists
// ---------------------------------------------------------------------------
__device__ __forceinline__ void warpArgMinB(float& v, int& i) {
    for (int off = 16; off; off >>= 1) {
        float ov = __shfl_down_sync(0xffffffffu, v, off);
        int   oi = __shfl_down_sync(0xffffffffu, i, off);
        if (ov < v || (ov == v && oi < i)) { v = ov; i = oi; }
    }
    v = __shfl_sync(0xffffffffu, v, 0);
    i = __shfl_sync(0xffffffffu, i, 0);
}

__global__ __launch_bounds__(512) void stageB2(float* __restrict__ out)
{
    int b = blockIdx.x;
    int tid = threadIdx.x, lane = tid & 31, wid = tid >> 5;   // 16 warps

    __shared__ unsigned long long s_match[Qn];
    __shared__ int                s_penk[Qn];      // # of +1e5f applications per row
    __shared__ unsigned long long s_or;
    __shared__ unsigned long long s_fb;
    __shared__ unsigned long long s_w2[16];
    __shared__ unsigned long long s_best2;

    const float* costB = g_costT + (size_t)b * Gn * Qn;
    const int*   gminB = g_gmin  + b * Qn;

    for (int q = tid; q < Qn; q += 512) { s_penk[q] = 0; s_match[q] = 0ull; }
    __syncthreads();

    // initial matches: first k entries of each gt's sorted cost list
    if (tid < Gn) {
        int bg = b * Gn + tid;
        int k = g_selk[bg];
        for (int p = 0; p < k; p++)
            atomicOr(&s_match[g_list[bg * LISTN + p]], 1ull << tid);
    }
    __syncthreads();

    // dedup (row penalty is row-constant => keep-gt == precomputed gmin)
    for (int q = tid; q < Qn; q += 512) {
        unsigned long long m = s_match[q];
        if (__popcll(m) > 1) s_match[q] = 1ull << gminB[q];
    }
    __syncthreads();

    // bounded force-match loop
    for (int iter = 0; iter < Gn; iter++) {
        if (tid == 0) { s_or = 0ull; s_fb = 0ull; }
        __syncthreads();
        unsigned long long loc = 0ull;
        for (int q = tid; q < Qn; q += 512) loc |= s_match[q];
        for (int off = 16; off; off >>= 1) loc |= __shfl_down_sync(0xffffffffu, loc, off);
        if (lane == 0) atomicOr(&s_or, loc);
        __syncthreads();
        unsigned long long unm = ~s_or;
        if (unm == 0ull) break;

        // penalize rows matched at iteration start
        for (int q = tid; q < Qn; q += 512)
            if (s_match[q] != 0ull) s_penk[q]++;
        __syncthreads();

        // each unmatched gt takes first never-penalized entry in its sorted list
        // (cost < 2e4 < 1e5 => reference argmin over cost+pen is among penk==0 rows;
        //  penk==0 rows picked this iteration by other gts remain pickable, as in ref)
        if (tid < Gn && ((unm >> tid) & 1ull)) {
            int bg = b * Gn + tid;
            bool found = false;
            for (int p = 0; p < LISTN; p++) {
                int q = g_list[bg * LISTN + p];
                if (s_penk[q] == 0) {
                    atomicOr(&s_match[q], 1ull << tid);
                    found = true;
                    break;
                }
            }
            if (!found) atomicOr(&s_fb, 1ull << tid);
        }
        __syncthreads();

        // exact fallback: full argmin with sequentially-accumulated fp32 penalties
        unsigned long long fb = s_fb;
        while (fb) {
            int g = __ffsll((long long)fb) - 1;
            fb &= fb - 1;
            const float* cg = costB + (size_t)g * Qn;
            unsigned long long bk = ~0ull;
            for (int q = tid; q < Qn; q += 512) {
                float v = cg[q];
                int k = s_penk[q];
                for (int i = 0; i < k; i++) v += 1e5f;    // replicate ref rounding
                unsigned long long key = ((unsigned long long)ordf(v) << 32) | (unsigned)q;
                if (key < bk) bk = key;
            }
            unsigned long long best = blockMinU64(bk, s_w2, &s_best2, lane, wid, 16);
            if (tid == 0) s_match[(unsigned int)(best & 0xffffffffu)] |= 1ull << g;
            __syncthreads();
        }

        // dedup
        for (int q = tid; q < Qn; q += 512) {
            unsigned long long m = s_match[q];
            if (__popcll(m) > 1) s_match[q] = 1ull << gminB[q];
        }
        __syncthreads();
    }

    // persist match state
    for (int q = tid; q < Qn; q += 512) g_match[b * Qn + q] = s_match[q];

    // matched_query_id [B,G]: argmin over matched rows of final penalized cost
    float* outI = out + (size_t)Bn * Qn * Gn + (size_t)b * Gn;
    for (int j = 0; j < 4; j++) {
        int g = (wid << 2) + j;
        const float* cc = costB + (size_t)g * Qn;
        float bv = 3.4e38f; int bi = 0x7fffffff;
        for (int q = lane; q < Qn; q += 32) {
            if ((s_match[q] >> g) & 1ull) {
                float v = cc[q];
                int k = s_penk[q];
                for (int i = 0; i < k; i++) v += 1e5f;
                if (v < bv || (v == bv && q < bi)) { bv = v; bi = q; }
            }
        }
        warpArgMinB(bv, bi);
        if (lane == 0) outI[g] = (bi == 0x7fffffff) ? 0.f : (float)bi;
    }
}

// ---------------------------------------------------------------------------
// Stage Out: expand bitmask to [B,Q,G] float matrix, float4 stores
// ---------------------------------------------------------------------------
__global__ __launch_bounds__(256) void stageOut(float* __restrict__ out)
{
    int idx = blockIdx.x * 256 + threadIdx.x;        // one float4 per thread
    int i = idx * 4;                                 // element index, < Bn*Qn*Gn
    int b = i / (Qn * Gn);
    int r = i - b * (Qn * Gn);
    int q = r >> 6, g = r & 63;                      // g multiple of 4
    unsigned long long m = g_match[b * Qn + q] >> g;
    float4 v;
    v.x = (m & 1ull) ? 1.f : 0.f;
    v.y = (m & 2ull) ? 1.f : 0.f;
    v.z = (m & 4ull) ? 1.f : 0.f;
    v.w = (m & 8ull) ? 1.f : 0.f;
    *reinterpret_cast<float4*>(out + i) = v;
}

// ---------------------------------------------------------------------------
extern "C" void kernel_launch(void* const* d_in, const int* in_sizes, int n_in,
                              void* d_out, int out_size)
{
    const float* logits = (const float*)d_in[0];
    const float* boxes  = (const float*)d_in[1];
    const int*   gtc    = (const int*)  d_in[2];
    const float* gtb    = (const float*)d_in[3];
    const float* szo    = (const float*)d_in[4];
    const float* szt    = (const float*)d_in[5];

    dim3 gA(Bn, (Qn + 127) / 128);
    stageA<<<gA, 128>>>(logits, boxes, gtc, gtb, szo, szt);
    stageSel<<<Bn * Gn, 256>>>();
    stageB2<<<Bn, 512>>>((float*)d_out);
    stageOut<<<(Bn * Qn * Gn / 4) / 256, 256>>>((float*)d_out);
}